// round 11
// baseline (speedup 1.0000x reference)
#include <cuda_runtime.h>
#include <cuda_fp16.h>
#include <cstdint>
#include <math.h>

#define SS 256
#define BB 64
#define HH 1024
#define VV 8192

// ---------------- scratch (device globals; no allocations allowed) ----------
__device__ float g_emb[SS * BB * HH];          // (S,B,H) embeddings + biases
__device__ float g_yT[(SS + 1) * HH * BB];     // slot s+1: h_s, layout [k][b]; slot0 = init
__device__ float g_wih_t[VV * HH];             // W_ih^T: [v][h]
__device__ int   g_isI64;
__device__ unsigned int g_ctr4[4];             // per-b-group step counters (rnn progress)

// fp16 GEMM images (K' = 1024):
__device__ __half g_a[(size_t)16384 * 1024];   // A = y fp16 [m][k], written by rnn warps
__device__ __half g_b[(size_t)8192 * 1024];    // B = fc_W fp16

typedef unsigned long long u64;

__device__ __forceinline__ u64 ffma2(u64 a, u64 b, u64 c) {
    u64 d;
    asm("fma.rn.f32x2 %0, %1, %2, %3;" : "=l"(d) : "l"(a), "l"(b), "l"(c));
    return d;
}
__device__ __forceinline__ u64 pack2(float x, float y) {
    u64 r;
    asm("mov.b64 %0, {%1, %2};" : "=l"(r) : "f"(x), "f"(y));
    return r;
}
__device__ __forceinline__ float2 unpack2(u64 v) {
    float2 f;
    asm("mov.b64 {%0, %1}, %2;" : "=f"(f.x), "=f"(f.y) : "l"(v));
    return f;
}
__device__ __forceinline__ u64 fadd2(u64 a, u64 b) {
    return ffma2(a, pack2(1.0f, 1.0f), b);
}
__device__ __forceinline__ uint32_t smem_u32(const void* p) {
    uint32_t a;
    asm("{ .reg .u64 t; cvta.to.shared.u64 t, %1; cvt.u32.u64 %0, t; }" : "=r"(a) : "l"(p));
    return a;
}
__device__ __forceinline__ unsigned pack_h2(float a, float b) {
    __half2 t = __floats2half2_rn(a, b);
    unsigned u;
    memcpy(&u, &t, 4);
    return u;
}
__device__ __forceinline__ void cpasync16(uint32_t dst, const void* src) {
    asm volatile("cp.async.cg.shared.global [%0], [%1], 16;" :: "r"(dst), "l"(src) : "memory");
}
#define CP_COMMIT() asm volatile("cp.async.commit_group;" ::: "memory")
#define CP_WAIT(n)  asm volatile("cp.async.wait_group %0;" :: "n"(n) : "memory")
#define BAR_RNN()   asm volatile("bar.sync 1, 256;" ::: "memory")
#define BAR_FC()    asm volatile("bar.sync 2, 256;" ::: "memory")

__device__ __forceinline__ void ldsm4(uint32_t* r, uint32_t addr) {
    asm volatile("ldmatrix.sync.aligned.m8n8.x4.shared.b16 {%0,%1,%2,%3}, [%4];"
                 : "=r"(r[0]), "=r"(r[1]), "=r"(r[2]), "=r"(r[3]) : "r"(addr));
}
__device__ __forceinline__ void mma16816(float* c, const uint32_t* a, const uint32_t* b) {
    asm volatile(
        "mma.sync.aligned.m16n8k16.row.col.f32.f16.f16.f32 "
        "{%0,%1,%2,%3}, {%4,%5,%6,%7}, {%8,%9}, {%0,%1,%2,%3};"
        : "+f"(c[0]), "+f"(c[1]), "+f"(c[2]), "+f"(c[3])
        : "r"(a[0]), "r"(a[1]), "r"(a[2]), "r"(a[3]), "r"(b[0]), "r"(b[1]));
}
__device__ __forceinline__ unsigned ld_acq(const unsigned int* p) {
    unsigned v;
    asm volatile("ld.acquire.gpu.global.u32 %0, [%1];" : "=r"(v) : "l"(p) : "memory");
    return v;
}

// ---------------- dtype detection --------------------------------------------
__global__ void detect_k(const unsigned int* __restrict__ xw) {
    __shared__ unsigned int red[256];
    unsigned int v = 0;
    for (int i = threadIdx.x; i < 8192; i += 256) v |= xw[2 * i + 1];
    red[threadIdx.x] = v;
    __syncthreads();
    for (int st = 128; st > 0; st >>= 1) {
        if (threadIdx.x < st) red[threadIdx.x] |= red[threadIdx.x + st];
        __syncthreads();
    }
    if (threadIdx.x == 0) g_isI64 = (red[0] == 0u) ? 1 : 0;
}

// ---------------- W_ih transpose ----------------------------------------------
__global__ void transpose_k(const float* __restrict__ in) {
    __shared__ float t[32][33];
    const int R = HH, C = VV;
    int c0 = blockIdx.x * 32, r0 = blockIdx.y * 32;
#pragma unroll
    for (int i = 0; i < 32; i += 8)
        t[threadIdx.y + i][threadIdx.x] =
            in[(size_t)(r0 + threadIdx.y + i) * C + c0 + threadIdx.x];
    __syncthreads();
#pragma unroll
    for (int i = 0; i < 32; i += 8)
        g_wih_t[(size_t)(c0 + threadIdx.y + i) * R + r0 + threadIdx.x] =
            t[threadIdx.x][threadIdx.y + i];
}

// ---------------- init ----------------------------------------------------------
__global__ void st0_k(const float* __restrict__ state) {
    int j = blockIdx.x * 256 + threadIdx.x;
    if (j < BB * HH) {
        int h = j >> 6, b = j & 63;
        g_yT[j] = state[(size_t)b * HH + h];
    }
    if (j < 4) g_ctr4[j] = 0u;
}

// ---------------- embedding gather + bias fold --------------------------------
__global__ void embed_k(const void* __restrict__ xraw,
                        const float* __restrict__ b_ih,
                        const float* __restrict__ b_hh) {
    int sb = blockIdx.x;
    int b = sb & (BB - 1);
    int s = sb >> 6;
    const int* xi = (const int*)xraw;
    long long pos = (long long)b * SS + s;
    int idx = g_isI64 ? xi[2 * pos] : xi[pos];
    int h4 = threadIdx.x * 4;
    float4 w  = *(const float4*)(g_wih_t + (size_t)idx * HH + h4);
    float4 bi = *(const float4*)(b_ih + h4);
    float4 bh = *(const float4*)(b_hh + h4);
    float4 o;
    o.x = w.x + bi.x + bh.x;
    o.y = w.y + bi.y + bh.y;
    o.z = w.z + bi.z + bh.z;
    o.w = w.w + bi.w + bh.w;
    *(float4*)(g_emb + (size_t)sb * HH + h4) = o;
}

// ---------------- conv_w: fc_W -> B fp16 ---------------------------------------
__global__ void conv_w_k(const float* __restrict__ fcW) {
    const int v = blockIdx.x;
    const int t = threadIdx.x;
    const float4* s4 = (const float4*)(fcW + (size_t)v * HH + t * 8);
    float4 va = s4[0], vb = s4[1];
    float f[8] = {va.x, va.y, va.z, va.w, vb.x, vb.y, vb.z, vb.w};
    unsigned hx[4];
#pragma unroll
    for (int p = 0; p < 4; p++)
        hx[p] = pack_h2(f[2 * p], f[2 * p + 1]);
    *(uint4*)(g_b + (size_t)v * 1024 + t * 8) = make_uint4(hx[0], hx[1], hx[2], hx[3]);
}

// ---------------- FUSED persistent kernel --------------------------------------
// 128 CTAs x 512 threads, one CTA per SM (smem 203KB).
//   warps 0-7  (tid 0..255)  : rnn recurrence (R7/R9 structure, W fp16 in smem)
//   warps 8-15 (tid 256..511): fc GEMM consumer, wavefront-follows rnn counters
// smem: sWh fp16 [k][32] 64KB | sH fp32 [k][16] 64KB (sR aliased) | fc 3x25600B
#define FC_STAGE   25600                   // A 64*80 + B 256*80
#define FUSED_SMEM (65536 + 65536 + 3 * FC_STAGE)

__global__ void __launch_bounds__(512, 1) fused_k(const float* __restrict__ W_hh,
                                                  const float* __restrict__ fcb,
                                                  float* __restrict__ out) {
    extern __shared__ char smraw[];
    __half* sWh = (__half*)smraw;                 // [k][32]
    float*  sH  = (float*)(smraw + 65536);        // [k][16]
    u64*    sR  = (u64*)sH;                       // aliased partials
    const uint32_t fcb0 = smem_u32(smraw + 131072);

    const int tid = threadIdx.x, cta = blockIdx.x;

    if (tid < 256) {
        // ================= rnn role =================
        const int lane = tid & 31;
        const int kh   = tid >> 5;
        const int bi = cta >> 5;
        const int n0 = (cta & 31) * 32;
        const int bbase = bi * 16;
        const uint32_t shH = smem_u32(sH);

        {   // W slice: sWh[k][n_l] = fp16(W_hh[n0+n_l][k])
            int nr = tid >> 3, ks = tid & 7;
            const float* wsrc = W_hh + (size_t)(n0 + nr) * HH;
#pragma unroll
            for (int j = 0; j < 32; j++) {
                int k4 = ks + j * 8;
                float4 w = *(const float4*)(wsrc + k4 * 4);
                sWh[(size_t)(k4 * 4 + 0) * 32 + nr] = __float2half_rn(w.x);
                sWh[(size_t)(k4 * 4 + 1) * 32 + nr] = __float2half_rn(w.y);
                sWh[(size_t)(k4 * 4 + 2) * 32 + nr] = __float2half_rn(w.z);
                sWh[(size_t)(k4 * 4 + 3) * 32 + nr] = __float2half_rn(w.w);
            }
        }
        BAR_RNN();

        const int rn = tid >> 3, rbp = tid & 7;
        const int eb = bbase + 2 * rbp;
        const int en = n0 + rn;

        const __half* wrow = sWh + (size_t)(kh * 128) * 32 + lane;
        const float*  hrow = sH + kh * 128 * 16;

        for (int s = 0; s < SS; s++) {
            const float* hsrc = g_yT + (size_t)s * (HH * BB) + bbase + (size_t)(kh * 128) * BB;
            const uint32_t sdst = shH + (uint32_t)(kh * 128) * 64;
#pragma unroll
            for (int i = 0; i < 16; i++) {
                int id = i * 32 + lane;
                int kl = id >> 2, bq = (id & 3) * 4;
                cpasync16(sdst + (uint32_t)(kl * 64 + bq * 4),
                          hsrc + (size_t)kl * BB + bq);
            }
            CP_COMMIT();

            const float* es = g_emb + (size_t)s * BB * HH;
            float e0 = es[(size_t)eb * HH + en];
            float e1 = es[(size_t)(eb + 1) * HH + en];

            CP_WAIT(0);
            __syncwarp();

            u64 acc[8];
#pragma unroll
            for (int bp = 0; bp < 8; bp++) acc[bp] = 0ull;

#pragma unroll 8
            for (int kk = 0; kk < 128; kk++) {
                float w = __half2float(wrow[(size_t)kk * 32]);
                u64 wd = pack2(w, w);
                const ulonglong2* hp = (const ulonglong2*)(hrow + kk * 16);
                ulonglong2 hA = hp[0], hB = hp[1], hC = hp[2], hD = hp[3];
                acc[0] = ffma2(hA.x, wd, acc[0]);
                acc[1] = ffma2(hA.y, wd, acc[1]);
                acc[2] = ffma2(hB.x, wd, acc[2]);
                acc[3] = ffma2(hB.y, wd, acc[3]);
                acc[4] = ffma2(hC.x, wd, acc[4]);
                acc[5] = ffma2(hC.y, wd, acc[5]);
                acc[6] = ffma2(hD.x, wd, acc[6]);
                acc[7] = ffma2(hD.y, wd, acc[7]);
            }
            BAR_RNN();                     // sH reads done before alias write

            u64* rp = sR + (size_t)kh * 256 + lane;
#pragma unroll
            for (int bp = 0; bp < 8; bp++) rp[bp * 32] = acc[bp];
            BAR_RNN();

            {
                const u64* q = sR + (size_t)rbp * 32 + rn;
                u64 v = q[0];
#pragma unroll
                for (int k2 = 1; k2 < 8; k2++) v = fadd2(v, q[(size_t)k2 * 256]);
                float2 f = unpack2(v);
                float2 o;
                o.x = tanhf(f.x + e0);
                o.y = tanhf(f.y + e1);
                *(float2*)(g_yT + (size_t)(s + 1) * (HH * BB) + (size_t)en * BB + eb) = o;
                g_a[(size_t)(s * 64 + eb) * 1024 + en]     = __float2half_rn(o.x);
                g_a[(size_t)(s * 64 + eb + 1) * 1024 + en] = __float2half_rn(o.y);
            }
            BAR_RNN();

            if (tid == 0) {
                asm volatile("red.release.gpu.global.add.u32 [%0], %1;"
                             :: "l"(&g_ctr4[bi]), "r"(1u) : "memory");
                unsigned v, target = 32u * (unsigned)(s + 1);
                do {
                    v = ld_acq(&g_ctr4[bi]);
                } while (v < target);
            }
            BAR_RNN();
        }
    } else {
        // ================= fc role =================
        // CTA tile 64m x 256n; 8 warps, warp tile 32m x 64n. 8192 tiles total.
        const int ft = tid - 256;
        const int lane = ft & 31, wid = ft >> 5;     // 0..7
        const int wm = wid & 1, wn = wid >> 1;

        const int arow = wm * 32 + (lane & 15);
        const int agq  = lane >> 4;
        const int brow = wn * 64 + (lane & 7) + ((lane >> 4) << 3);
        const int bgq  = (lane >> 3) & 1;
        const int lrow = ft >> 2, lg = ft & 3;       // loaders

        int ready_mt = -1;

        for (int t = cta; t < 8192; t += 128) {
            const int mt = t >> 5, ntile = t & 31;
            const int m0 = mt * 64, n0 = ntile * 256;

            if (mt > ready_mt) {
                if (ft == 0) {
                    unsigned target = 32u * (unsigned)(mt + 1);
                    for (;;) {
                        unsigned a0 = ld_acq(&g_ctr4[0]);
                        unsigned a1 = ld_acq(&g_ctr4[1]);
                        unsigned a2 = ld_acq(&g_ctr4[2]);
                        unsigned a3 = ld_acq(&g_ctr4[3]);
                        if (a0 >= target && a1 >= target && a2 >= target && a3 >= target) break;
                        __nanosleep(256);
                    }
                }
                BAR_FC();
                ready_mt = mt;
            }

            float acc[2][8][4];
#pragma unroll
            for (int i = 0; i < 2; i++)
#pragma unroll
                for (int j = 0; j < 8; j++)
#pragma unroll
                    for (int q = 0; q < 4; q++) acc[i][j][q] = 0.0f;

#define FC_ISSUE(c, st) do {                                                              \
        uint32_t sa = fcb0 + (st) * FC_STAGE;                                             \
        uint32_t sb = sa + 5120;                                                          \
        const __half* pa = g_a + (size_t)m0 * 1024 + (c) * 32;                            \
        const __half* pb = g_b + (size_t)n0 * 1024 + (c) * 32;                            \
        cpasync16(sa + lrow * 80 + lg * 16,        pa + (size_t)lrow * 1024 + lg * 8);        \
        cpasync16(sb + lrow * 80 + lg * 16,        pb + (size_t)lrow * 1024 + lg * 8);        \
        cpasync16(sb + (lrow + 64) * 80 + lg * 16, pb + (size_t)(lrow + 64) * 1024 + lg * 8); \
        cpasync16(sb + (lrow + 128) * 80 + lg * 16, pb + (size_t)(lrow + 128) * 1024 + lg * 8); \
        cpasync16(sb + (lrow + 192) * 80 + lg * 16, pb + (size_t)(lrow + 192) * 1024 + lg * 8); \
    } while (0)

            FC_ISSUE(0, 0); CP_COMMIT();
            FC_ISSUE(1, 1); CP_COMMIT();

            for (int c = 0; c < 32; c++) {
                const int st = c % 3;
                CP_WAIT(1);
                BAR_FC();
                if (c + 2 < 32) FC_ISSUE(c + 2, (c + 2) % 3);
                CP_COMMIT();

                uint32_t sa = fcb0 + st * FC_STAGE;
                uint32_t sb = sa + 5120;
#pragma unroll
                for (int kt = 0; kt < 2; kt++) {
                    uint32_t afr[2][4], bfr[4][4];
#pragma unroll
                    for (int m2 = 0; m2 < 2; m2++)
                        ldsm4(afr[m2], sa + (uint32_t)((arow + m2 * 16) * 80 + (kt * 2 + agq) * 16));
#pragma unroll
                    for (int bt = 0; bt < 4; bt++)
                        ldsm4(bfr[bt], sb + (uint32_t)((brow + bt * 16) * 80 + (kt * 2 + bgq) * 16));
#pragma unroll
                    for (int m2 = 0; m2 < 2; m2++)
#pragma unroll
                        for (int nt = 0; nt < 8; nt++)
                            mma16816(acc[m2][nt], afr[m2], &bfr[nt >> 1][(nt & 1) * 2]);
                }
            }
            CP_WAIT(0);

#pragma unroll
            for (int m2 = 0; m2 < 2; m2++) {
                int row = m0 + wm * 32 + m2 * 16 + (lane >> 2);
#pragma unroll
                for (int nt = 0; nt < 8; nt++) {
                    int col = n0 + wn * 64 + nt * 8 + 2 * (lane & 3);
                    float2 bias = *(const float2*)(fcb + col);
                    float2 v0, v1;
                    v0.x = acc[m2][nt][0] + bias.x;
                    v0.y = acc[m2][nt][1] + bias.y;
                    v1.x = acc[m2][nt][2] + bias.x;
                    v1.y = acc[m2][nt][3] + bias.y;
                    *(float2*)(out + (size_t)row * VV + col) = v0;
                    *(float2*)(out + (size_t)(row + 8) * VV + col) = v1;
                }
            }
            BAR_FC();
        }
    }
}

// ---------------- final state copy --------------------------------------------
__global__ void copy_state_k(float* __restrict__ dst) {
    int j = blockIdx.x * 256 + threadIdx.x;
    if (j < BB * HH) {
        float v = g_yT[(size_t)SS * HH * BB + j];
        int h = j >> 6, b = j & 63;
        dst[(size_t)b * HH + h] = v;
    }
}

// ---------------- launch --------------------------------------------------------
extern "C" void kernel_launch(void* const* d_in, const int* in_sizes, int n_in,
                              void* d_out, int out_size) {
    const void*  x     = d_in[0];
    const float* state = (const float*)d_in[1];
    const float* W_ih  = (const float*)d_in[2];
    const float* W_hh  = (const float*)d_in[3];
    const float* b_ih  = (const float*)d_in[4];
    const float* b_hh  = (const float*)d_in[5];
    const float* fc_W  = (const float*)d_in[6];
    const float* fc_b  = (const float*)d_in[7];
    float* out = (float*)d_out;
    (void)in_sizes; (void)n_in; (void)out_size;

    static int attr_set = 0;
    if (!attr_set) {
        cudaFuncSetAttribute(fused_k,
                             cudaFuncAttributeMaxDynamicSharedMemorySize,
                             FUSED_SMEM);
        attr_set = 1;
    }

    detect_k<<<1, 256>>>((const unsigned int*)x);
    transpose_k<<<dim3(VV / 32, HH / 32), dim3(32, 8)>>>(W_ih);
    st0_k<<<256, 256>>>(state);
    embed_k<<<SS * BB, 256>>>(x, b_ih, b_hh);
    conv_w_k<<<VV, 128>>>(fc_W);
    fused_k<<<128, 512, FUSED_SMEM>>>(W_hh, fc_b, out);
    copy_state_k<<<256, 256>>>(out + (size_t)SS * BB * VV);
}

// round 12
// speedup vs baseline: 1.7106x; 1.7106x over previous
#include <cuda_runtime.h>
#include <cuda_fp16.h>
#include <cstdint>
#include <math.h>

#define SS 256
#define BB 64
#define HH 1024
#define VV 8192

// ---------------- scratch (device globals; no allocations allowed) ----------
__device__ float g_emb[SS * BB * HH];          // (S,B,H) embeddings + biases
__device__ float g_wih_t[VV * HH];             // W_ih^T: [v][h]
__device__ float g_hN[BB * HH];                // final hidden state fp32 [b][h]
__device__ __half g_h0[BB * HH];               // initial state fp16 [b][h]
__device__ int   g_isI64;
__device__ unsigned int g_ctr4[4];             // per-b-group step counters

// fp16 GEMM images (K' = 1024):
__device__ __half g_a[(size_t)16384 * 1024];   // h fp16 [m=s*64+b][k]; rnn writes, fc reads
__device__ __half g_b[(size_t)8192 * 1024];    // fc_W fp16

typedef unsigned long long u64;

__device__ __forceinline__ uint32_t smem_u32(const void* p) {
    uint32_t a;
    asm("{ .reg .u64 t; cvta.to.shared.u64 t, %1; cvt.u32.u64 %0, t; }" : "=r"(a) : "l"(p));
    return a;
}
__device__ __forceinline__ unsigned pack_h2(float a, float b) {
    __half2 t = __floats2half2_rn(a, b);
    unsigned u;
    memcpy(&u, &t, 4);
    return u;
}
__device__ __forceinline__ void cpasync16(uint32_t dst, const void* src) {
    asm volatile("cp.async.cg.shared.global [%0], [%1], 16;" :: "r"(dst), "l"(src) : "memory");
}
#define CP_COMMIT() asm volatile("cp.async.commit_group;" ::: "memory")
#define CP_WAIT(n)  asm volatile("cp.async.wait_group %0;" :: "n"(n) : "memory")

__device__ __forceinline__ void ldsm4(uint32_t* r, uint32_t addr) {
    asm volatile("ldmatrix.sync.aligned.m8n8.x4.shared.b16 {%0,%1,%2,%3}, [%4];"
                 : "=r"(r[0]), "=r"(r[1]), "=r"(r[2]), "=r"(r[3]) : "r"(addr));
}
__device__ __forceinline__ void mma16816(float* c, const uint32_t* a, const uint32_t* b) {
    asm volatile(
        "mma.sync.aligned.m16n8k16.row.col.f32.f16.f16.f32 "
        "{%0,%1,%2,%3}, {%4,%5,%6,%7}, {%8,%9}, {%0,%1,%2,%3};"
        : "+f"(c[0]), "+f"(c[1]), "+f"(c[2]), "+f"(c[3])
        : "r"(a[0]), "r"(a[1]), "r"(a[2]), "r"(a[3]), "r"(b[0]), "r"(b[1]));
}
__device__ __forceinline__ unsigned ld_acq(const unsigned int* p) {
    unsigned v;
    asm volatile("ld.acquire.gpu.global.u32 %0, [%1];" : "=r"(v) : "l"(p) : "memory");
    return v;
}

// ---------------- dtype detection --------------------------------------------
__global__ void detect_k(const unsigned int* __restrict__ xw) {
    __shared__ unsigned int red[256];
    unsigned int v = 0;
    for (int i = threadIdx.x; i < 8192; i += 256) v |= xw[2 * i + 1];
    red[threadIdx.x] = v;
    __syncthreads();
    for (int st = 128; st > 0; st >>= 1) {
        if (threadIdx.x < st) red[threadIdx.x] |= red[threadIdx.x + st];
        __syncthreads();
    }
    if (threadIdx.x == 0) g_isI64 = (red[0] == 0u) ? 1 : 0;
}

// ---------------- W_ih transpose ----------------------------------------------
__global__ void transpose_k(const float* __restrict__ in) {
    __shared__ float t[32][33];
    const int R = HH, C = VV;
    int c0 = blockIdx.x * 32, r0 = blockIdx.y * 32;
#pragma unroll
    for (int i = 0; i < 32; i += 8)
        t[threadIdx.y + i][threadIdx.x] =
            in[(size_t)(r0 + threadIdx.y + i) * C + c0 + threadIdx.x];
    __syncthreads();
#pragma unroll
    for (int i = 0; i < 32; i += 8)
        g_wih_t[(size_t)(c0 + threadIdx.y + i) * R + r0 + threadIdx.x] =
            t[threadIdx.x][threadIdx.y + i];
}

// ---------------- init: state -> g_h0 fp16, reset counters --------------------
__global__ void st0_k(const float* __restrict__ state) {
    int j = blockIdx.x * 256 + threadIdx.x;
    if (j < BB * HH) g_h0[j] = __float2half_rn(state[j]);
    if (j < 4) g_ctr4[j] = 0u;
}

// ---------------- embedding gather + bias fold --------------------------------
__global__ void embed_k(const void* __restrict__ xraw,
                        const float* __restrict__ b_ih,
                        const float* __restrict__ b_hh) {
    int sb = blockIdx.x;
    int b = sb & (BB - 1);
    int s = sb >> 6;
    const int* xi = (const int*)xraw;
    long long pos = (long long)b * SS + s;
    int idx = g_isI64 ? xi[2 * pos] : xi[pos];
    int h4 = threadIdx.x * 4;
    float4 w  = *(const float4*)(g_wih_t + (size_t)idx * HH + h4);
    float4 bi = *(const float4*)(b_ih + h4);
    float4 bh = *(const float4*)(b_hh + h4);
    float4 o;
    o.x = w.x + bi.x + bh.x;
    o.y = w.y + bi.y + bh.y;
    o.z = w.z + bi.z + bh.z;
    o.w = w.w + bi.w + bh.w;
    *(float4*)(g_emb + (size_t)sb * HH + h4) = o;
}

// ---------------- conv_w: fc_W -> B fp16 ---------------------------------------
__global__ void conv_w_k(const float* __restrict__ fcW) {
    const int v = blockIdx.x;
    const int t = threadIdx.x;
    const float4* s4 = (const float4*)(fcW + (size_t)v * HH + t * 8);
    float4 va = s4[0], vb = s4[1];
    unsigned hx[4];
    hx[0] = pack_h2(va.x, va.y);
    hx[1] = pack_h2(va.z, va.w);
    hx[2] = pack_h2(vb.x, vb.y);
    hx[3] = pack_h2(vb.z, vb.w);
    *(uint4*)(g_b + (size_t)v * 1024 + t * 8) = make_uint4(hx[0], hx[1], hx[2], hx[3]);
}

// ---------------- persistent recurrence via tensor cores ----------------------
// 128 CTAs = 4 b-groups(16b=M) x 32 n-blocks(32n=N), 256 threads = 8 warps
// (k-slices of 128). Per step: 16x32x1024 GEMM as mma.m16n8k16 fp16, k-split
// over warps, fp32 partial reduction in smem, tanh, write h fp16 to g_a.
// smem: sW fp16 [32n][1032] 66048B | sA [8 warps][16b][136] 34816B | sR 16896B
#define RNN_SW_B  66048
#define RNN_SA_B  34816
#define RNN_SR_F  (8 * 528)
#define RNN_SMEM  (RNN_SW_B + RNN_SA_B + RNN_SR_F * 4)

__global__ void __launch_bounds__(256, 1) rnn_mma_k(const float* __restrict__ W_hh) {
    extern __shared__ char smraw[];
    const uint32_t sW0 = smem_u32(smraw);                     // W fp16, row stride 2064B
    const uint32_t sA0 = sW0 + RNN_SW_B;                      // A staging, warp regions
    float* sR = (float*)(smraw + RNN_SW_B + RNN_SA_B);        // partials [w][b*33+n]

    const int tid = threadIdx.x, cta = blockIdx.x;
    const int lane = tid & 31;
    const int kh   = tid >> 5;                 // warp = k-slice (0..7)
    const int bi = cta >> 5;
    const int n0 = (cta & 31) * 32;
    const int bbase = bi * 16;

    // Load W slice: sW[n][k] = fp16(W_hh[n0+n][k]) for n in [0,32), k in [0,1024)
    {
        int nrow = tid >> 3, kseg = (tid & 7) * 128;
        const float* wsrc = W_hh + (size_t)(n0 + nrow) * HH + kseg;
        uint32_t wdst = sW0 + (uint32_t)nrow * 2064 + (uint32_t)kseg * 2;
#pragma unroll
        for (int j = 0; j < 16; j++) {
            float4 w1 = *(const float4*)(wsrc + j * 8);
            float4 w2 = *(const float4*)(wsrc + j * 8 + 4);
            uint4 hv = make_uint4(pack_h2(w1.x, w1.y), pack_h2(w1.z, w1.w),
                                  pack_h2(w2.x, w2.y), pack_h2(w2.z, w2.w));
            asm volatile("st.shared.v4.b32 [%0], {%1,%2,%3,%4};"
                         :: "r"(wdst + j * 16), "r"(hv.x), "r"(hv.y), "r"(hv.z), "r"(hv.w)
                         : "memory");
        }
    }
    __syncthreads();

    // fragment addressing (identical scheme to validated fc kernel)
    const int arow = lane & 15;
    const int agq  = lane >> 4;
    const int brow = (lane & 7) + ((lane >> 4) << 3);
    const int bgq  = (lane >> 3) & 1;
    const uint32_t sAw = sA0 + (uint32_t)kh * 4352;           // 16 rows x 272B

    // accumulator output mapping (standard m16n8 C layout)
    const int c_b = lane >> 2;
    const int c_n = 2 * (lane & 3);

    // reduce-phase mapping
    const int rn = tid >> 3;                   // 0..31 local n
    const int rb = (tid & 7) * 2;              // 0..14 local b pair
    const int en = n0 + rn;
    const int eb = bbase + rb;

    for (int s = 0; s < SS; s++) {
        // stage A: h fp16 [16b][128k] for this warp's k-slice
        const __half* hsrc = (s == 0) ? (g_h0 + (size_t)bbase * HH)
                                      : (g_a + ((size_t)(s - 1) * 64 + bbase) * 1024);
#pragma unroll
        for (int i = 0; i < 8; i++) {
            int id = i * 32 + lane;            // 0..255
            int row = id >> 4, c16 = id & 15;
            cpasync16(sAw + (uint32_t)(row * 272 + c16 * 16),
                      hsrc + (size_t)row * 1024 + kh * 128 + c16 * 8);
        }
        CP_COMMIT();

        // emb prefetch
        const float* es = g_emb + (size_t)s * BB * HH;
        float e0 = es[(size_t)eb * HH + en];
        float e1 = es[(size_t)(eb + 1) * HH + en];

        CP_WAIT(0);
        __syncwarp();

        float acc[4][4];
#pragma unroll
        for (int i = 0; i < 4; i++)
#pragma unroll
            for (int q = 0; q < 4; q++) acc[i][q] = 0.0f;

#pragma unroll
        for (int kt = 0; kt < 8; kt++) {
            uint32_t afr[4], bfr[2][4];
            ldsm4(afr, sAw + (uint32_t)(arow * 272 + kt * 32 + agq * 16));
#pragma unroll
            for (int bt = 0; bt < 2; bt++)
                ldsm4(bfr[bt], sW0 + (uint32_t)((brow + bt * 16) * 2064
                                                + kh * 256 + kt * 32 + bgq * 16));
#pragma unroll
            for (int nt = 0; nt < 4; nt++)
                mma16816(acc[nt], afr, &bfr[nt >> 1][(nt & 1) * 2]);
        }

        // partials -> sR[kh][b*33 + n]
        float* rw = sR + kh * 528;
#pragma unroll
        for (int nt = 0; nt < 4; nt++) {
            int n = nt * 8 + c_n;
            rw[c_b * 33 + n]           = acc[nt][0];
            rw[c_b * 33 + n + 1]       = acc[nt][1];
            rw[(c_b + 8) * 33 + n]     = acc[nt][2];
            rw[(c_b + 8) * 33 + n + 1] = acc[nt][3];
        }
        __syncthreads();

        // reduce over 8 warps, add emb, tanh, write h fp16 (g_a)
        {
            float s0 = 0.0f, s1 = 0.0f;
#pragma unroll
            for (int w = 0; w < 8; w++) {
                s0 += sR[w * 528 + rb * 33 + rn];
                s1 += sR[w * 528 + (rb + 1) * 33 + rn];
            }
            float o0 = tanhf(s0 + e0);
            float o1 = tanhf(s1 + e1);
            size_t m = (size_t)s * 64 + eb;
            g_a[m * 1024 + en]       = __float2half_rn(o0);
            g_a[(m + 1) * 1024 + en] = __float2half_rn(o1);
            if (s == SS - 1) {
                g_hN[(size_t)eb * HH + en]       = o0;
                g_hN[(size_t)(eb + 1) * HH + en] = o1;
            }
        }
        __syncthreads();

        // per-b-group barrier (release publishes g_a stores)
        if (tid == 0) {
            asm volatile("red.release.gpu.global.add.u32 [%0], %1;"
                         :: "l"(&g_ctr4[bi]), "r"(1u) : "memory");
            unsigned v, target = 32u * (unsigned)(s + 1);
            do {
                v = ld_acq(&g_ctr4[bi]);
            } while (v < target);
        }
        __syncthreads();
    }
}

// ---------------- fc GEMM via mma.sync fp16, K'=1024 (R9 proven) --------------
#define FC_A_BYTES 10240
#define FC_STAGE   30720
#define FC_SMEM    (FC_STAGE * 3)

__global__ void __launch_bounds__(256, 1) fc_mma_k(const float* __restrict__ fcb,
                                                   float* __restrict__ out) {
    extern __shared__ char dsm[];
    const int tid = threadIdx.x, lane = tid & 31, wid = tid >> 5;
    const int wm = wid & 1, wn = wid >> 1;
    const int n0 = blockIdx.x * 256, m0 = blockIdx.y * 128;
    const uint32_t sbase = smem_u32(dsm);

    float acc[4][8][4];
#pragma unroll
    for (int i = 0; i < 4; i++)
#pragma unroll
        for (int j = 0; j < 8; j++)
#pragma unroll
            for (int q = 0; q < 4; q++) acc[i][j][q] = 0.0f;

    const int lr = tid >> 2, lg = tid & 3;

#define FC_ISSUE(c, st) do {                                                              \
        uint32_t sa = sbase + (st) * FC_STAGE;                                            \
        uint32_t sb = sa + FC_A_BYTES;                                                    \
        const __half* pa = g_a + (size_t)m0 * 1024 + (c) * 32;                            \
        const __half* pb = g_b + (size_t)n0 * 1024 + (c) * 32;                            \
        cpasync16(sa + lr * 80 + lg * 16,          pa + (size_t)lr * 1024 + lg * 8);          \
        cpasync16(sa + (lr + 64) * 80 + lg * 16,   pa + (size_t)(lr + 64) * 1024 + lg * 8);   \
        cpasync16(sb + lr * 80 + lg * 16,          pb + (size_t)lr * 1024 + lg * 8);          \
        cpasync16(sb + (lr + 64) * 80 + lg * 16,   pb + (size_t)(lr + 64) * 1024 + lg * 8);   \
        cpasync16(sb + (lr + 128) * 80 + lg * 16,  pb + (size_t)(lr + 128) * 1024 + lg * 8);  \
        cpasync16(sb + (lr + 192) * 80 + lg * 16,  pb + (size_t)(lr + 192) * 1024 + lg * 8);  \
    } while (0)

    FC_ISSUE(0, 0); CP_COMMIT();
    FC_ISSUE(1, 1); CP_COMMIT();

    const int arow = wm * 64 + (lane & 15);
    const int agq  = lane >> 4;
    const int brow = wn * 64 + (lane & 7) + ((lane >> 4) << 3);
    const int bgq  = (lane >> 3) & 1;

    for (int c = 0; c < 32; c++) {
        const int st = c % 3;
        CP_WAIT(1);
        __syncthreads();
        if (c + 2 < 32) FC_ISSUE(c + 2, (c + 2) % 3);
        CP_COMMIT();

        uint32_t sa = sbase + st * FC_STAGE;
        uint32_t sb = sa + FC_A_BYTES;
#pragma unroll
        for (int kt = 0; kt < 2; kt++) {
            uint32_t afr[4][4], bfr[4][4];
#pragma unroll
            for (int mt = 0; mt < 4; mt++)
                ldsm4(afr[mt], sa + (uint32_t)((arow + mt * 16) * 80 + (kt * 2 + agq) * 16));
#pragma unroll
            for (int bt = 0; bt < 4; bt++)
                ldsm4(bfr[bt], sb + (uint32_t)((brow + bt * 16) * 80 + (kt * 2 + bgq) * 16));
#pragma unroll
            for (int mt = 0; mt < 4; mt++)
#pragma unroll
                for (int nt = 0; nt < 8; nt++)
                    mma16816(acc[mt][nt], afr[mt], &bfr[nt >> 1][(nt & 1) * 2]);
        }
    }

#pragma unroll
    for (int mt = 0; mt < 4; mt++) {
        int row = m0 + wm * 64 + mt * 16 + (lane >> 2);
#pragma unroll
        for (int nt = 0; nt < 8; nt++) {
            int col = n0 + wn * 64 + nt * 8 + 2 * (lane & 3);
            float2 bias = *(const float2*)(fcb + col);
            float2 v0, v1;
            v0.x = acc[mt][nt][0] + bias.x;
            v0.y = acc[mt][nt][1] + bias.y;
            v1.x = acc[mt][nt][2] + bias.x;
            v1.y = acc[mt][nt][3] + bias.y;
            *(float2*)(out + (size_t)row * VV + col) = v0;
            *(float2*)(out + (size_t)(row + 8) * VV + col) = v1;
        }
    }
}

// ---------------- final state copy --------------------------------------------
__global__ void copy_state_k(float* __restrict__ dst) {
    int j = blockIdx.x * 256 + threadIdx.x;
    if (j < BB * HH) dst[j] = g_hN[j];
}

// ---------------- launch --------------------------------------------------------
extern "C" void kernel_launch(void* const* d_in, const int* in_sizes, int n_in,
                              void* d_out, int out_size) {
    const void*  x     = d_in[0];
    const float* state = (const float*)d_in[1];
    const float* W_ih  = (const float*)d_in[2];
    const float* W_hh  = (const float*)d_in[3];
    const float* b_ih  = (const float*)d_in[4];
    const float* b_hh  = (const float*)d_in[5];
    const float* fc_W  = (const float*)d_in[6];
    const float* fc_b  = (const float*)d_in[7];
    float* out = (float*)d_out;
    (void)in_sizes; (void)n_in; (void)out_size;

    static int attr_set = 0;
    if (!attr_set) {
        cudaFuncSetAttribute(rnn_mma_k,
                             cudaFuncAttributeMaxDynamicSharedMemorySize,
                             RNN_SMEM);
        cudaFuncSetAttribute(fc_mma_k,
                             cudaFuncAttributeMaxDynamicSharedMemorySize,
                             FC_SMEM);
        attr_set = 1;
    }

    detect_k<<<1, 256>>>((const unsigned int*)x);
    transpose_k<<<dim3(VV / 32, HH / 32), dim3(32, 8)>>>(W_ih);
    st0_k<<<256, 256>>>(state);
    embed_k<<<SS * BB, 256>>>(x, b_ih, b_hh);
    conv_w_k<<<VV, 128>>>(fc_W);
    rnn_mma_k<<<128, 256, RNN_SMEM>>>(W_hh);
    fc_mma_k<<<dim3(VV / 256, (SS * BB) / 128), 256, FC_SMEM>>>(fc_b, out);
    copy_state_k<<<256, 256>>>(out + (size_t)SS * BB * VV);
}